// round 16
// baseline (speedup 1.0000x reference)
#include <cuda_runtime.h>
#include <cuda_fp16.h>
#include <cstdint>

// Problem constants (fixed shapes per reference)
#define NNODES 50000
#define MAXE   800000
#define DF     128
#define SLOT   96        // per-node CSR bucket capacity (Poisson(16) max ~42)
#define GSMS   148       // persistent GEMM grid

// ---------------- device scratch (no allocations allowed) ----------------
__device__ int g_fmt;                  // 1 => edge_index int64, 0 => int32
__device__ int g_deg[NNODES];          // doubles as fill cursor
__device__ __align__(16) int g_csr[(size_t)NNODES * SLOT];
__device__ __align__(16) unsigned char g_zero[16];   // static-zero cp.async source

__device__ __align__(16) __half g_xb[(size_t)NNODES * DF];
__device__ __align__(16) __half g_meanb[(size_t)NNODES * DF];
__device__ __align__(16) __half g_hAb[(size_t)NNODES * DF];
__device__ __align__(16) __half g_hBb[(size_t)NNODES * DF];
// Concatenated f16 weights: wcat1[128][256] ([W1l|W1r]), wcat2[128][256],
// wcat3[64][256] ([W3l|W3r])
__device__ __align__(16) __half g_wb[2 * 128 * 256 + 64 * 256];

__device__ __forceinline__ uint32_t smem_u32(const void* p) {
    uint32_t a;
    asm("{ .reg .u64 t; cvta.to.shared.u64 t, %1; cvt.u32.u64 %0, t; }" : "=r"(a) : "l"(p));
    return a;
}

// ---------------- one-shot prep: conversions + init + out zero ------------
__global__ void k_prep(const float* __restrict__ x,
                       const unsigned int* __restrict__ ew,
                       const float* __restrict__ W1l, const float* __restrict__ W1r,
                       const float* __restrict__ W2l, const float* __restrict__ W2r,
                       const float* __restrict__ W3l, const float* __restrict__ W3r,
                       float* __restrict__ out) {
    int gid = blockIdx.x * blockDim.x + threadIdx.x;
    const int XN4 = NNODES * DF / 4;            // 400000 float4

    if (gid < XN4) {
        float4 v = reinterpret_cast<const float4*>(x)[gid];
        __half2 lo = __floats2half2_rn(v.x, v.y);
        __half2 hi = __floats2half2_rn(v.z, v.w);
        uint2 o;
        o.x = *reinterpret_cast<unsigned int*>(&lo);
        o.y = *reinterpret_cast<unsigned int*>(&hi);
        reinterpret_cast<uint2*>(g_xb)[gid] = o;
    }
    // build concatenated weights: 20480 uint2 (4 f16) destinations
    if (gid < 20480) {
        const float* l;
        const float* r;
        int n, k;
        if (gid < 8192)       { l = W1l; r = W1r; n = gid >> 6;            k = (gid & 63) * 4; }
        else if (gid < 16384) { l = W2l; r = W2r; n = (gid - 8192) >> 6;   k = (gid & 63) * 4; }
        else                  { l = W3l; r = W3r; n = (gid - 16384) >> 6;  k = (gid & 63) * 4; }
        const float* src = (k < 128) ? (l + n * 128 + k) : (r + n * 128 + k - 128);
        float4 v = *reinterpret_cast<const float4*>(src);
        __half2 lo = __floats2half2_rn(v.x, v.y);
        __half2 hi = __floats2half2_rn(v.z, v.w);
        uint2 o;
        o.x = *reinterpret_cast<unsigned int*>(&lo);
        o.y = *reinterpret_cast<unsigned int*>(&hi);
        reinterpret_cast<uint2*>(g_wb)[gid] = o;
    }
    if (gid < NNODES) g_deg[gid] = 0;
    if (gid < 64)     out[gid] = 0.f;
    if (blockIdx.x == 0) {
        __shared__ int flag;
        if (threadIdx.x == 0) flag = 0;
        __syncthreads();
        for (int i = threadIdx.x; i < 1024; i += blockDim.x)
            if (ew[2 * i + 1] != 0u) flag = 1;   // benign race
        __syncthreads();
        if (threadIdx.x == 0) g_fmt = flag ? 0 : 1;
    }
}

// ---------------- single-pass bucketed CSR fill (2 edges/thread) ----------
__global__ void k_fill(const void* __restrict__ eptr, int E) {
    int t = blockIdx.x * blockDim.x + threadIdx.x;
    int e = t * 2;
    if (e >= E) return;
    int s0, d0, s1, d1;
    if (g_fmt) {
        const long long* p = (const long long*)eptr;
        longlong2 sv = *reinterpret_cast<const longlong2*>(p + e);
        longlong2 dv = *reinterpret_cast<const longlong2*>(p + E + e);
        s0 = (int)sv.x; s1 = (int)sv.y;
        d0 = (int)dv.x; d1 = (int)dv.y;
    } else {
        const int* p = (const int*)eptr;
        int2 sv = *reinterpret_cast<const int2*>(p + e);
        int2 dv = *reinterpret_cast<const int2*>(p + E + e);
        s0 = sv.x; s1 = sv.y;
        d0 = dv.x; d1 = dv.y;
    }
    int p0 = atomicAdd(&g_deg[d0], 1);
    if (p0 < SLOT) g_csr[(size_t)d0 * SLOT + p0] = s0;
    if (e + 1 < E) {
        int p1 = atomicAdd(&g_deg[d1], 1);
        if (p1 < SLOT) g_csr[(size_t)d1 * SLOT + p1] = s1;
    }
}

// ---------------- mean aggregation (f16 gather, fp32 accum, f16 out) -------
__global__ void k_agg(const __half* __restrict__ hin, __half* __restrict__ meanout) {
    int warp = threadIdx.x >> 5;
    int lane = threadIdx.x & 31;
    int node = blockIdx.x * 8 + warp;
    if (node >= NNODES) return;
    int deg = g_deg[node];
    if (deg > SLOT) deg = SLOT;
    const int* row = g_csr + (size_t)node * SLOT;
    const __half* base = hin + lane * 4;
    float4 acc = make_float4(0.f, 0.f, 0.f, 0.f);
#define ACC4(u) { \
        float2 f0 = __half22float2(*reinterpret_cast<__half2*>(&u.x)); \
        float2 f1 = __half22float2(*reinterpret_cast<__half2*>(&u.y)); \
        acc.x += f0.x; acc.y += f0.y; acc.z += f1.x; acc.w += f1.y; }
    int i = 0;
    for (; i + 8 <= deg; i += 8) {
        int4 sa = *reinterpret_cast<const int4*>(row + i);
        int4 sb = *reinterpret_cast<const int4*>(row + i + 4);
        uint2 u[8];
        u[0] = *reinterpret_cast<const uint2*>(base + (size_t)sa.x * DF);
        u[1] = *reinterpret_cast<const uint2*>(base + (size_t)sa.y * DF);
        u[2] = *reinterpret_cast<const uint2*>(base + (size_t)sa.z * DF);
        u[3] = *reinterpret_cast<const uint2*>(base + (size_t)sa.w * DF);
        u[4] = *reinterpret_cast<const uint2*>(base + (size_t)sb.x * DF);
        u[5] = *reinterpret_cast<const uint2*>(base + (size_t)sb.y * DF);
        u[6] = *reinterpret_cast<const uint2*>(base + (size_t)sb.z * DF);
        u[7] = *reinterpret_cast<const uint2*>(base + (size_t)sb.w * DF);
#pragma unroll
        for (int j = 0; j < 8; j++) ACC4(u[j])
    }
    for (; i < deg; i++) {
        int s = __ldg(&row[i]);
        uint2 u = *reinterpret_cast<const uint2*>(base + (size_t)s * DF);
        ACC4(u)
    }
#undef ACC4
    float inv = (deg > 0) ? 1.f / (float)deg : 0.f;
    __half2 lo = __floats2half2_rn(acc.x * inv, acc.y * inv);
    __half2 hi = __floats2half2_rn(acc.z * inv, acc.w * inv);
    uint2 o;
    o.x = *reinterpret_cast<unsigned int*>(&lo);
    o.y = *reinterpret_cast<unsigned int*>(&hi);
    *reinterpret_cast<uint2*>(meanout + (size_t)node * DF + lane * 4) = o;
}

// ---------------- persistent double-buffered tensor-core GEMM (f16 acc) ----
// out[row][col] = sigmoid( [mean||h][row] · Wcat[col] + b[col] )
// 148 CTAs x 512 threads persistent; B staged once, A double-buffered via
// cp.async; fragments via ldmatrix.x4; mma.sync m16n8k16 f16 accumulation
// (2x legacy rate, half the accumulator regs). Bias+sigmoid in fp32 at the
// epilogue. LAST fuses sigmoid + global column-sum into out[64] (fp32).
template <int DOUT, bool LAST>
__global__ void __launch_bounds__(512, 1)
k_gemm(const __half* __restrict__ meanin, const __half* __restrict__ hin,
       const __half* __restrict__ Wcat, const float* __restrict__ bias,
       void* __restrict__ outp, int ntiles) {
    constexpr int BM = 128;
    constexpr int SA = 264;
    constexpr int SW = 264;
    constexpr int WN = DOUT / 32;       // warps along N (4 or 2)
    constexpr int WM = 16 / WN;         // warps along M (4 or 8)
    constexpr int MT = BM / (WM * 16);  // m16 tiles per warp (2 or 1)

    extern __shared__ __align__(16) char smraw[];
    __half* Bs = reinterpret_cast<__half*>(smraw);    // DOUT*SW
    __half* A0 = Bs + DOUT * SW;                      // BM*SA
    __half* A1 = A0 + BM * SA;                        // BM*SA
    float* bs = reinterpret_cast<float*>(A1 + BM * SA);  // DOUT
    __shared__ float so[64];

    int tid = threadIdx.x;
    if (LAST && tid < 64) so[tid] = 0.f;
    if (tid < DOUT) bs[tid] = bias[tid];

    // stage B once: DOUT rows x 32 uint4 chunks (full K=256 row)
    for (int i = tid; i < DOUT * 32; i += 512) {
        int n = i >> 5, c = i & 31;
        uint4 v = reinterpret_cast<const uint4*>(Wcat)[n * 32 + c];
        *reinterpret_cast<uint4*>(&Bs[n * SW + c * 8]) = v;
    }

    int lane = tid & 31, wid = tid >> 5;
    int gid = lane >> 2, tg = lane & 3;
    int wm = wid / WN, wn = wid % WN;
    int rowb = wm * (MT * 16);
    int ncolb = wn * 32;

    // ldmatrix source addresses (lane-dependent), +kk*32B per k-step
    uint32_t b_addr[2];
#pragma unroll
    for (int ntp = 0; ntp < 2; ntp++) {
        int m = lane >> 3;
        int brow = ncolb + ntp * 16 + ((m >> 1) << 3) + (lane & 7);
        b_addr[ntp] = smem_u32(Bs) + (uint32_t)(brow * SW + (m & 1) * 8) * 2;
    }
    int arow_off = lane & 15;
    int ahalf = (lane >> 4) * 8;

    auto prefetch = [&](int tile, __half* Ab) {
        int row0 = tile * BM;
        uint32_t abase = smem_u32(Ab);
        for (int i = tid; i < BM * 32; i += 512) {
            int r = i >> 5, c = i & 31;
            int row = row0 + r;
            const void* g;
            if (row < NNODES) {
                g = (c < 16) ? (const void*)(meanin + (size_t)row * 128 + c * 8)
                             : (const void*)(hin    + (size_t)row * 128 + (c - 16) * 8);
            } else {
                g = (const void*)g_zero;
            }
            uint32_t dst = abase + (uint32_t)(r * SA + c * 8) * 2;
            asm volatile("cp.async.cg.shared.global [%0], [%1], 16;"
                         :: "r"(dst), "l"(g));
        }
        asm volatile("cp.async.commit_group;" ::: "memory");
    };

    if (blockIdx.x < ntiles) prefetch(blockIdx.x, A0);

    int j = 0;
    for (int t = blockIdx.x; t < ntiles; t += gridDim.x, j++) {
        int tn = t + gridDim.x;
        if (tn < ntiles) {
            prefetch(tn, (j & 1) ? A0 : A1);
            asm volatile("cp.async.wait_group 1;" ::: "memory");
        } else {
            asm volatile("cp.async.wait_group 0;" ::: "memory");
        }
        __syncthreads();
        const __half* As = (j & 1) ? A1 : A0;
        int row0 = t * BM;

        uint32_t a_addr[MT];
#pragma unroll
        for (int mt = 0; mt < MT; mt++)
            a_addr[mt] = smem_u32(As) +
                (uint32_t)((rowb + mt * 16 + arow_off) * SA + ahalf) * 2;

        // f16 accumulators: 2 b32 regs per (mt, nt) = {d0,d1},{d2,d3}
        unsigned int c[MT][4][2];
#pragma unroll
        for (int mt = 0; mt < MT; mt++)
#pragma unroll
            for (int nt = 0; nt < 4; nt++) { c[mt][nt][0] = 0u; c[mt][nt][1] = 0u; }

#pragma unroll
        for (int kk = 0; kk < 16; kk++) {
            unsigned int bf[4][2];
            asm volatile("ldmatrix.sync.aligned.m8n8.x4.shared.b16 {%0,%1,%2,%3}, [%4];"
                         : "=r"(bf[0][0]), "=r"(bf[0][1]), "=r"(bf[1][0]), "=r"(bf[1][1])
                         : "r"(b_addr[0] + kk * 32));
            asm volatile("ldmatrix.sync.aligned.m8n8.x4.shared.b16 {%0,%1,%2,%3}, [%4];"
                         : "=r"(bf[2][0]), "=r"(bf[2][1]), "=r"(bf[3][0]), "=r"(bf[3][1])
                         : "r"(b_addr[1] + kk * 32));
#pragma unroll
            for (int mt = 0; mt < MT; mt++) {
                unsigned int a0, a1, a2, a3;
                asm volatile("ldmatrix.sync.aligned.m8n8.x4.shared.b16 {%0,%1,%2,%3}, [%4];"
                             : "=r"(a0), "=r"(a1), "=r"(a2), "=r"(a3)
                             : "r"(a_addr[mt] + kk * 32));
#pragma unroll
                for (int nt = 0; nt < 4; nt++) {
                    asm volatile(
                        "mma.sync.aligned.m16n8k16.row.col.f16.f16.f16.f16 "
                        "{%0,%1}, {%2,%3,%4,%5}, {%6,%7}, {%0,%1};"
                        : "+r"(c[mt][nt][0]), "+r"(c[mt][nt][1])
                        : "r"(a0), "r"(a1), "r"(a2), "r"(a3),
                          "r"(bf[nt][0]), "r"(bf[nt][1]));
                }
            }
        }

        if (!LAST) {
            __half* out = reinterpret_cast<__half*>(outp);
#pragma unroll
            for (int mt = 0; mt < MT; mt++) {
                int ro = row0 + rowb + mt * 16 + gid;
#pragma unroll
                for (int nt = 0; nt < 4; nt++) {
                    int col = ncolb + nt * 8 + tg * 2;
                    float b0 = bs[col], b1 = bs[col + 1];
                    if (ro < NNODES) {
                        float2 f = __half22float2(*reinterpret_cast<__half2*>(&c[mt][nt][0]));
                        float v0 = 1.f / (1.f + __expf(-(f.x + b0)));
                        float v1 = 1.f / (1.f + __expf(-(f.y + b1)));
                        __half2 pv = __floats2half2_rn(v0, v1);
                        *reinterpret_cast<__half2*>(&out[(size_t)ro * DOUT + col]) = pv;
                    }
                    if (ro + 8 < NNODES) {
                        float2 f = __half22float2(*reinterpret_cast<__half2*>(&c[mt][nt][1]));
                        float v2 = 1.f / (1.f + __expf(-(f.x + b0)));
                        float v3 = 1.f / (1.f + __expf(-(f.y + b1)));
                        __half2 pv = __floats2half2_rn(v2, v3);
                        *reinterpret_cast<__half2*>(&out[(size_t)(ro + 8) * DOUT + col]) = pv;
                    }
                }
            }
        } else {
            int ro = row0 + rowb + gid;
#pragma unroll
            for (int nt = 0; nt < 4; nt++) {
                int col = ncolb + nt * 8 + tg * 2;
                float b0 = bs[col], b1 = bs[col + 1];
                float t0 = 0.f, t1 = 0.f;
                if (ro < NNODES) {
                    float2 f = __half22float2(*reinterpret_cast<__half2*>(&c[0][nt][0]));
                    t0 += 1.f / (1.f + __expf(-(f.x + b0)));
                    t1 += 1.f / (1.f + __expf(-(f.y + b1)));
                }
                if (ro + 8 < NNODES) {
                    float2 f = __half22float2(*reinterpret_cast<__half2*>(&c[0][nt][1]));
                    t0 += 1.f / (1.f + __expf(-(f.x + b0)));
                    t1 += 1.f / (1.f + __expf(-(f.y + b1)));
                }
#pragma unroll
                for (int o = 4; o < 32; o <<= 1) {
                    t0 += __shfl_xor_sync(0xFFFFFFFFu, t0, o);
                    t1 += __shfl_xor_sync(0xFFFFFFFFu, t1, o);
                }
                if (lane < 4) {
                    atomicAdd(&so[col], t0);
                    atomicAdd(&so[col + 1], t1);
                }
            }
        }
        __syncthreads();   // protect A buffer before next prefetch reuses it
    }

    if (LAST) {
        if (tid < 64) atomicAdd(&reinterpret_cast<float*>(outp)[tid], so[tid]);
    }
}

// ---------------- launch ----------------
extern "C" void kernel_launch(void* const* d_in, const int* in_sizes, int n_in,
                              void* d_out, int out_size) {
    const float* x    = (const float*)d_in[0];
    const void*  eidx = d_in[1];
    const float* W1l  = (const float*)d_in[2];
    const float* b1   = (const float*)d_in[3];
    const float* W1r  = (const float*)d_in[4];
    const float* W2l  = (const float*)d_in[5];
    const float* b2   = (const float*)d_in[6];
    const float* W2r  = (const float*)d_in[7];
    const float* W3l  = (const float*)d_in[8];
    const float* b3   = (const float*)d_in[9];
    const float* W3r  = (const float*)d_in[10];

    int E = in_sizes[1] / 2;
    if (E > MAXE) E = MAXE;

    void *pXB, *pMB, *pAB, *pBB, *pWB;
    cudaGetSymbolAddress(&pXB, g_xb);
    cudaGetSymbolAddress(&pMB, g_meanb);
    cudaGetSymbolAddress(&pAB, g_hAb);
    cudaGetSymbolAddress(&pBB, g_hBb);
    cudaGetSymbolAddress(&pWB, g_wb);
    __half* xb    = (__half*)pXB;
    __half* meanb = (__half*)pMB;
    __half* hAb   = (__half*)pAB;
    __half* hBb   = (__half*)pBB;
    __half* wb    = (__half*)pWB;
    __half* wc1 = wb;                       // 128*256
    __half* wc2 = wb + 128 * 256;           // 128*256
    __half* wc3 = wb + 2 * 128 * 256;       // 64*256

    const int smem12 = (128 * 264 + 2 * 128 * 264) * 2 + 128 * 4;  // 203264
    const int smem3  = (64 * 264 + 2 * 128 * 264) * 2 + 64 * 4;    // 169472
    cudaFuncSetAttribute(k_gemm<128, false>, cudaFuncAttributeMaxDynamicSharedMemorySize, smem12);
    cudaFuncSetAttribute(k_gemm<64,  true>,  cudaFuncAttributeMaxDynamicSharedMemorySize, smem3);

    int fgrid  = (E / 2 + 255) / 256;
    int agrid  = (NNODES + 7) / 8;
    int ntiles = (NNODES + 127) / 128;
    int pgrid  = (NNODES * DF / 4 + 255) / 256;

    // order: prep(1), fill(2), agg(3), gemm(4) <- ncu capture on gemm layer 1
    k_prep<<<pgrid, 256>>>(x, (const unsigned int*)eidx,
                           W1l, W1r, W2l, W2r, W3l, W3r, (float*)d_out);
    k_fill<<<fgrid, 256>>>(eidx, E);
    // layer 1
    k_agg<<<agrid, 256>>>(xb, meanb);
    k_gemm<128, false><<<GSMS, 512, smem12>>>(meanb, xb, wc1, b1, hAb, ntiles);
    // layer 2
    k_agg<<<agrid, 256>>>(hAb, meanb);
    k_gemm<128, false><<<GSMS, 512, smem12>>>(meanb, hAb, wc2, b2, hBb, ntiles);
    // layer 3 + fused global sum
    k_agg<<<agrid, 256>>>(hBb, meanb);
    k_gemm<64, true><<<GSMS, 512, smem3>>>(meanb, hBb, wc3, b3, d_out, ntiles);
}

// round 17
// speedup vs baseline: 1.0845x; 1.0845x over previous
#include <cuda_runtime.h>
#include <cuda_fp16.h>
#include <cstdint>

// Problem constants (fixed shapes per reference)
#define NNODES 50000
#define MAXE   800000
#define DF     128
#define SLOT   96        // per-node CSR bucket capacity (Poisson(16) max ~42)
#define GSMS   148       // persistent GEMM grid

// ---------------- device scratch (no allocations allowed) ----------------
__device__ int g_fmt;                  // 1 => edge_index int64, 0 => int32
__device__ int g_deg[NNODES];          // doubles as fill cursor
__device__ __align__(16) int g_csr[(size_t)NNODES * SLOT];
__device__ __align__(16) unsigned char g_zero[16];   // static-zero cp.async source

__device__ __align__(16) __half g_xb[(size_t)NNODES * DF];
__device__ __align__(16) __half g_meanb[(size_t)NNODES * DF];
__device__ __align__(16) __half g_hAb[(size_t)NNODES * DF];
__device__ __align__(16) __half g_hBb[(size_t)NNODES * DF];
// Concatenated f16 weights: wcat1[128][256] ([W1l|W1r]), wcat2[128][256],
// wcat3[64][256] ([W3l|W3r])
__device__ __align__(16) __half g_wb[2 * 128 * 256 + 64 * 256];

__device__ __forceinline__ uint32_t smem_u32(const void* p) {
    uint32_t a;
    asm("{ .reg .u64 t; cvta.to.shared.u64 t, %1; cvt.u32.u64 %0, t; }" : "=r"(a) : "l"(p));
    return a;
}

// ---------------- one-shot prep: conversions + init + out zero ------------
__global__ void k_prep(const float* __restrict__ x,
                       const unsigned int* __restrict__ ew,
                       const float* __restrict__ W1l, const float* __restrict__ W1r,
                       const float* __restrict__ W2l, const float* __restrict__ W2r,
                       const float* __restrict__ W3l, const float* __restrict__ W3r,
                       float* __restrict__ out) {
    int gid = blockIdx.x * blockDim.x + threadIdx.x;
    const int XN4 = NNODES * DF / 4;            // 400000 float4

    if (gid < XN4) {
        float4 v = reinterpret_cast<const float4*>(x)[gid];
        __half2 lo = __floats2half2_rn(v.x, v.y);
        __half2 hi = __floats2half2_rn(v.z, v.w);
        uint2 o;
        o.x = *reinterpret_cast<unsigned int*>(&lo);
        o.y = *reinterpret_cast<unsigned int*>(&hi);
        reinterpret_cast<uint2*>(g_xb)[gid] = o;
    }
    // build concatenated weights: 20480 uint2 (4 f16) destinations
    if (gid < 20480) {
        const float* l;
        const float* r;
        int n, k;
        if (gid < 8192)       { l = W1l; r = W1r; n = gid >> 6;            k = (gid & 63) * 4; }
        else if (gid < 16384) { l = W2l; r = W2r; n = (gid - 8192) >> 6;   k = (gid & 63) * 4; }
        else                  { l = W3l; r = W3r; n = (gid - 16384) >> 6;  k = (gid & 63) * 4; }
        const float* src = (k < 128) ? (l + n * 128 + k) : (r + n * 128 + k - 128);
        float4 v = *reinterpret_cast<const float4*>(src);
        __half2 lo = __floats2half2_rn(v.x, v.y);
        __half2 hi = __floats2half2_rn(v.z, v.w);
        uint2 o;
        o.x = *reinterpret_cast<unsigned int*>(&lo);
        o.y = *reinterpret_cast<unsigned int*>(&hi);
        reinterpret_cast<uint2*>(g_wb)[gid] = o;
    }
    if (gid < NNODES) g_deg[gid] = 0;
    if (gid < 64)     out[gid] = 0.f;
    if (blockIdx.x == 0) {
        __shared__ int flag;
        if (threadIdx.x == 0) flag = 0;
        __syncthreads();
        for (int i = threadIdx.x; i < 1024; i += blockDim.x)
            if (ew[2 * i + 1] != 0u) flag = 1;   // benign race
        __syncthreads();
        if (threadIdx.x == 0) g_fmt = flag ? 0 : 1;
    }
}

// ---------------- single-pass bucketed CSR fill (2 edges/thread) ----------
__global__ void k_fill(const void* __restrict__ eptr, int E) {
    int t = blockIdx.x * blockDim.x + threadIdx.x;
    int e = t * 2;
    if (e >= E) return;
    int s0, d0, s1, d1;
    if (g_fmt) {
        const long long* p = (const long long*)eptr;
        longlong2 sv = *reinterpret_cast<const longlong2*>(p + e);
        longlong2 dv = *reinterpret_cast<const longlong2*>(p + E + e);
        s0 = (int)sv.x; s1 = (int)sv.y;
        d0 = (int)dv.x; d1 = (int)dv.y;
    } else {
        const int* p = (const int*)eptr;
        int2 sv = *reinterpret_cast<const int2*>(p + e);
        int2 dv = *reinterpret_cast<const int2*>(p + E + e);
        s0 = sv.x; s1 = sv.y;
        d0 = dv.x; d1 = dv.y;
    }
    int p0 = atomicAdd(&g_deg[d0], 1);
    if (p0 < SLOT) g_csr[(size_t)d0 * SLOT + p0] = s0;
    if (e + 1 < E) {
        int p1 = atomicAdd(&g_deg[d1], 1);
        if (p1 < SLOT) g_csr[(size_t)d1 * SLOT + p1] = s1;
    }
}

// ---------------- mean aggregation (f16 gather, HADD2 accum) ---------------
// Features are f16; accumulate with packed half2 adds (2 HADD2 per uint2
// instead of 4 cvt + 4 FADD). deg<=96, |h|<=~8 -> sums well within f16 range.
// Mean scaling done in fp32 for the final division.
__global__ void k_agg(const __half* __restrict__ hin, __half* __restrict__ meanout) {
    int warp = threadIdx.x >> 5;
    int lane = threadIdx.x & 31;
    int node = blockIdx.x * 8 + warp;
    if (node >= NNODES) return;
    int deg = g_deg[node];
    if (deg > SLOT) deg = SLOT;
    const int* row = g_csr + (size_t)node * SLOT;
    const __half* base = hin + lane * 4;
    __half2 a0 = __float2half2_rn(0.f);
    __half2 a1 = __float2half2_rn(0.f);
#define ACCH(u) { \
        a0 = __hadd2(a0, *reinterpret_cast<__half2*>(&u.x)); \
        a1 = __hadd2(a1, *reinterpret_cast<__half2*>(&u.y)); }
    int i = 0;
    for (; i + 8 <= deg; i += 8) {
        int4 sa = *reinterpret_cast<const int4*>(row + i);
        int4 sb = *reinterpret_cast<const int4*>(row + i + 4);
        uint2 u[8];
        u[0] = *reinterpret_cast<const uint2*>(base + (size_t)sa.x * DF);
        u[1] = *reinterpret_cast<const uint2*>(base + (size_t)sa.y * DF);
        u[2] = *reinterpret_cast<const uint2*>(base + (size_t)sa.z * DF);
        u[3] = *reinterpret_cast<const uint2*>(base + (size_t)sa.w * DF);
        u[4] = *reinterpret_cast<const uint2*>(base + (size_t)sb.x * DF);
        u[5] = *reinterpret_cast<const uint2*>(base + (size_t)sb.y * DF);
        u[6] = *reinterpret_cast<const uint2*>(base + (size_t)sb.z * DF);
        u[7] = *reinterpret_cast<const uint2*>(base + (size_t)sb.w * DF);
#pragma unroll
        for (int j = 0; j < 8; j++) ACCH(u[j])
    }
    for (; i < deg; i++) {
        int s = __ldg(&row[i]);
        uint2 u = *reinterpret_cast<const uint2*>(base + (size_t)s * DF);
        ACCH(u)
    }
#undef ACCH
    float inv = (deg > 0) ? 1.f / (float)deg : 0.f;
    float2 f0 = __half22float2(a0);
    float2 f1 = __half22float2(a1);
    __half2 lo = __floats2half2_rn(f0.x * inv, f0.y * inv);
    __half2 hi = __floats2half2_rn(f1.x * inv, f1.y * inv);
    uint2 o;
    o.x = *reinterpret_cast<unsigned int*>(&lo);
    o.y = *reinterpret_cast<unsigned int*>(&hi);
    *reinterpret_cast<uint2*>(meanout + (size_t)node * DF + lane * 4) = o;
}

// ---------------- persistent double-buffered tensor-core GEMM (f16 acc) ----
// out[row][col] = sigmoid( [mean||h][row] · Wcat[col] + b[col] )
// 148 CTAs x 512 threads persistent; B staged once, A double-buffered via
// cp.async; fragments via ldmatrix.x4; mma.sync m16n8k16 f16 accumulation.
// Bias+sigmoid in fp32 at the epilogue. LAST fuses global sum into out[64].
template <int DOUT, bool LAST>
__global__ void __launch_bounds__(512, 1)
k_gemm(const __half* __restrict__ meanin, const __half* __restrict__ hin,
       const __half* __restrict__ Wcat, const float* __restrict__ bias,
       void* __restrict__ outp, int ntiles) {
    constexpr int BM = 128;
    constexpr int SA = 264;
    constexpr int SW = 264;
    constexpr int WN = DOUT / 32;       // warps along N (4 or 2)
    constexpr int WM = 16 / WN;         // warps along M (4 or 8)
    constexpr int MT = BM / (WM * 16);  // m16 tiles per warp (2 or 1)

    extern __shared__ __align__(16) char smraw[];
    __half* Bs = reinterpret_cast<__half*>(smraw);    // DOUT*SW
    __half* A0 = Bs + DOUT * SW;                      // BM*SA
    __half* A1 = A0 + BM * SA;                        // BM*SA
    float* bs = reinterpret_cast<float*>(A1 + BM * SA);  // DOUT
    __shared__ float so[64];

    int tid = threadIdx.x;
    if (LAST && tid < 64) so[tid] = 0.f;
    if (tid < DOUT) bs[tid] = bias[tid];

    // stage B once: DOUT rows x 32 uint4 chunks (full K=256 row)
    for (int i = tid; i < DOUT * 32; i += 512) {
        int n = i >> 5, c = i & 31;
        uint4 v = reinterpret_cast<const uint4*>(Wcat)[n * 32 + c];
        *reinterpret_cast<uint4*>(&Bs[n * SW + c * 8]) = v;
    }

    int lane = tid & 31, wid = tid >> 5;
    int gid = lane >> 2, tg = lane & 3;
    int wm = wid / WN, wn = wid % WN;
    int rowb = wm * (MT * 16);
    int ncolb = wn * 32;

    // ldmatrix source addresses (lane-dependent), +kk*32B per k-step
    uint32_t b_addr[2];
#pragma unroll
    for (int ntp = 0; ntp < 2; ntp++) {
        int m = lane >> 3;
        int brow = ncolb + ntp * 16 + ((m >> 1) << 3) + (lane & 7);
        b_addr[ntp] = smem_u32(Bs) + (uint32_t)(brow * SW + (m & 1) * 8) * 2;
    }
    int arow_off = lane & 15;
    int ahalf = (lane >> 4) * 8;

    auto prefetch = [&](int tile, __half* Ab) {
        int row0 = tile * BM;
        uint32_t abase = smem_u32(Ab);
        for (int i = tid; i < BM * 32; i += 512) {
            int r = i >> 5, c = i & 31;
            int row = row0 + r;
            const void* g;
            if (row < NNODES) {
                g = (c < 16) ? (const void*)(meanin + (size_t)row * 128 + c * 8)
                             : (const void*)(hin    + (size_t)row * 128 + (c - 16) * 8);
            } else {
                g = (const void*)g_zero;
            }
            uint32_t dst = abase + (uint32_t)(r * SA + c * 8) * 2;
            asm volatile("cp.async.cg.shared.global [%0], [%1], 16;"
                         :: "r"(dst), "l"(g));
        }
        asm volatile("cp.async.commit_group;" ::: "memory");
    };

    if (blockIdx.x < ntiles) prefetch(blockIdx.x, A0);

    int j = 0;
    for (int t = blockIdx.x; t < ntiles; t += gridDim.x, j++) {
        int tn = t + gridDim.x;
        if (tn < ntiles) {
            prefetch(tn, (j & 1) ? A0 : A1);
            asm volatile("cp.async.wait_group 1;" ::: "memory");
        } else {
            asm volatile("cp.async.wait_group 0;" ::: "memory");
        }
        __syncthreads();
        const __half* As = (j & 1) ? A1 : A0;
        int row0 = t * BM;

        uint32_t a_addr[MT];
#pragma unroll
        for (int mt = 0; mt < MT; mt++)
            a_addr[mt] = smem_u32(As) +
                (uint32_t)((rowb + mt * 16 + arow_off) * SA + ahalf) * 2;

        // f16 accumulators: 2 b32 regs per (mt, nt) = {d0,d1},{d2,d3}
        unsigned int c[MT][4][2];
#pragma unroll
        for (int mt = 0; mt < MT; mt++)
#pragma unroll
            for (int nt = 0; nt < 4; nt++) { c[mt][nt][0] = 0u; c[mt][nt][1] = 0u; }

#pragma unroll
        for (int kk = 0; kk < 16; kk++) {
            unsigned int bf[4][2];
            asm volatile("ldmatrix.sync.aligned.m8n8.x4.shared.b16 {%0,%1,%2,%3}, [%4];"
                         : "=r"(bf[0][0]), "=r"(bf[0][1]), "=r"(bf[1][0]), "=r"(bf[1][1])
                         : "r"(b_addr[0] + kk * 32));
            asm volatile("ldmatrix.sync.aligned.m8n8.x4.shared.b16 {%0,%1,%2,%3}, [%4];"
                         : "=r"(bf[2][0]), "=r"(bf[2][1]), "=r"(bf[3][0]), "=r"(bf[3][1])
                         : "r"(b_addr[1] + kk * 32));
#pragma unroll
            for (int mt = 0; mt < MT; mt++) {
                unsigned int a0, a1, a2, a3;
                asm volatile("ldmatrix.sync.aligned.m8n8.x4.shared.b16 {%0,%1,%2,%3}, [%4];"
                             : "=r"(a0), "=r"(a1), "=r"(a2), "=r"(a3)
                             : "r"(a_addr[mt] + kk * 32));
#pragma unroll
                for (int nt = 0; nt < 4; nt++) {
                    asm volatile(
                        "mma.sync.aligned.m16n8k16.row.col.f16.f16.f16.f16 "
                        "{%0,%1}, {%2,%3,%4,%5}, {%6,%7}, {%0,%1};"
                        : "+r"(c[mt][nt][0]), "+r"(c[mt][nt][1])
                        : "r"(a0), "r"(a1), "r"(a2), "r"(a3),
                          "r"(bf[nt][0]), "r"(bf[nt][1]));
                }
            }
        }

        if (!LAST) {
            __half* out = reinterpret_cast<__half*>(outp);
#pragma unroll
            for (int mt = 0; mt < MT; mt++) {
                int ro = row0 + rowb + mt * 16 + gid;
#pragma unroll
                for (int nt = 0; nt < 4; nt++) {
                    int col = ncolb + nt * 8 + tg * 2;
                    float b0 = bs[col], b1 = bs[col + 1];
                    if (ro < NNODES) {
                        float2 f = __half22float2(*reinterpret_cast<__half2*>(&c[mt][nt][0]));
                        float v0 = 1.f / (1.f + __expf(-(f.x + b0)));
                        float v1 = 1.f / (1.f + __expf(-(f.y + b1)));
                        __half2 pv = __floats2half2_rn(v0, v1);
                        *reinterpret_cast<__half2*>(&out[(size_t)ro * DOUT + col]) = pv;
                    }
                    if (ro + 8 < NNODES) {
                        float2 f = __half22float2(*reinterpret_cast<__half2*>(&c[mt][nt][1]));
                        float v2 = 1.f / (1.f + __expf(-(f.x + b0)));
                        float v3 = 1.f / (1.f + __expf(-(f.y + b1)));
                        __half2 pv = __floats2half2_rn(v2, v3);
                        *reinterpret_cast<__half2*>(&out[(size_t)(ro + 8) * DOUT + col]) = pv;
                    }
                }
            }
        } else {
            int ro = row0 + rowb + gid;
#pragma unroll
            for (int nt = 0; nt < 4; nt++) {
                int col = ncolb + nt * 8 + tg * 2;
                float b0 = bs[col], b1 = bs[col + 1];
                float t0 = 0.f, t1 = 0.f;
                if (ro < NNODES) {
                    float2 f = __half22float2(*reinterpret_cast<__half2*>(&c[0][nt][0]));
                    t0 += 1.f / (1.f + __expf(-(f.x + b0)));
                    t1 += 1.f / (1.f + __expf(-(f.y + b1)));
                }
                if (ro + 8 < NNODES) {
                    float2 f = __half22float2(*reinterpret_cast<__half2*>(&c[0][nt][1]));
                    t0 += 1.f / (1.f + __expf(-(f.x + b0)));
                    t1 += 1.f / (1.f + __expf(-(f.y + b1)));
                }
#pragma unroll
                for (int o = 4; o < 32; o <<= 1) {
                    t0 += __shfl_xor_sync(0xFFFFFFFFu, t0, o);
                    t1 += __shfl_xor_sync(0xFFFFFFFFu, t1, o);
                }
                if (lane < 4) {
                    atomicAdd(&so[col], t0);
                    atomicAdd(&so[col + 1], t1);
                }
            }
        }
        __syncthreads();   // protect A buffer before next prefetch reuses it
    }

    if (LAST) {
        if (tid < 64) atomicAdd(&reinterpret_cast<float*>(outp)[tid], so[tid]);
    }
}

// ---------------- launch ----------------
extern "C" void kernel_launch(void* const* d_in, const int* in_sizes, int n_in,
                              void* d_out, int out_size) {
    const float* x    = (const float*)d_in[0];
    const void*  eidx = d_in[1];
    const float* W1l  = (const float*)d_in[2];
    const float* b1   = (const float*)d_in[3];
    const float* W1r  = (const float*)d_in[4];
    const float* W2l  = (const float*)d_in[5];
    const float* b2   = (const float*)d_in[6];
    const float* W2r  = (const float*)d_in[7];
    const float* W3l  = (const float*)d_in[8];
    const float* b3   = (const float*)d_in[9];
    const float* W3r  = (const float*)d_in[10];

    int E = in_sizes[1] / 2;
    if (E > MAXE) E = MAXE;

    void *pXB, *pMB, *pAB, *pBB, *pWB;
    cudaGetSymbolAddress(&pXB, g_xb);
    cudaGetSymbolAddress(&pMB, g_meanb);
    cudaGetSymbolAddress(&pAB, g_hAb);
    cudaGetSymbolAddress(&pBB, g_hBb);
    cudaGetSymbolAddress(&pWB, g_wb);
    __half* xb    = (__half*)pXB;
    __half* meanb = (__half*)pMB;
    __half* hAb   = (__half*)pAB;
    __half* hBb   = (__half*)pBB;
    __half* wb    = (__half*)pWB;
    __half* wc1 = wb;                       // 128*256
    __half* wc2 = wb + 128 * 256;           // 128*256
    __half* wc3 = wb + 2 * 128 * 256;       // 64*256

    const int smem12 = (128 * 264 + 2 * 128 * 264) * 2 + 128 * 4;  // 203264
    const int smem3  = (64 * 264 + 2 * 128 * 264) * 2 + 64 * 4;    // 169472
    cudaFuncSetAttribute(k_gemm<128, false>, cudaFuncAttributeMaxDynamicSharedMemorySize, smem12);
    cudaFuncSetAttribute(k_gemm<64,  true>,  cudaFuncAttributeMaxDynamicSharedMemorySize, smem3);

    int fgrid  = (E / 2 + 255) / 256;
    int agrid  = (NNODES + 7) / 8;
    int ntiles = (NNODES + 127) / 128;
    int pgrid  = (NNODES * DF / 4 + 255) / 256;

    // order: prep(1), fill(2), agg(3), gemm(4) <- ncu capture on gemm layer 1
    k_prep<<<pgrid, 256>>>(x, (const unsigned int*)eidx,
                           W1l, W1r, W2l, W2r, W3l, W3r, (float*)d_out);
    k_fill<<<fgrid, 256>>>(eidx, E);
    // layer 1
    k_agg<<<agrid, 256>>>(xb, meanb);
    k_gemm<128, false><<<GSMS, 512, smem12>>>(meanb, xb, wc1, b1, hAb, ntiles);
    // layer 2
    k_agg<<<agrid, 256>>>(hAb, meanb);
    k_gemm<128, false><<<GSMS, 512, smem12>>>(meanb, hAb, wc2, b2, hBb, ntiles);
    // layer 3 + fused global sum
    k_agg<<<agrid, 256>>>(hBb, meanb);
    k_gemm<64, true><<<GSMS, 512, smem3>>>(meanb, hBb, wc3, b3, d_out, ntiles);
}